// round 3
// baseline (speedup 1.0000x reference)
#include <cuda_runtime.h>

// Problem constants: B=32, C=8, H=256, W=256
#define NMAPS    256         // B*C
#define NBLOCKS  1024        // 4 quarter-map blocks per map
#define NTHREADS 256
#define QUART_F4 4096        // float4s per quarter-map (16384 elems)

// Per-block partials (no allocation: __device__ globals).
__device__ float        g_s [NBLOCKS];
__device__ float        g_sx[NBLOCKS];
__device__ float        g_sy[NBLOCKS];
__device__ float        g_m [NBLOCKS];
__device__ int          g_i [NBLOCKS];
__device__ unsigned int g_count = 0;

__device__ __forceinline__ void accum4(float4 a, float4 t, int e0,
                                       float& s, float& sx, float& sy,
                                       float& tmax, int& tidx) {
    int col = e0 & 255;
    int row = e0 >> 8;
    float ex = __expf(a.x);
    float ey = __expf(a.y);
    float ez = __expf(a.z);
    float ew = __expf(a.w);
    float es = (ex + ey) + (ez + ew);
    s  += es;
    sy  = fmaf(es, (float)(row + 1), sy);
    float extra = fmaf(2.f, ez, ey);
    extra = fmaf(3.f, ew, extra);
    sx += fmaf(es, (float)(col + 1), extra);
    if (t.x > tmax) { tmax = t.x; tidx = e0;     }
    if (t.y > tmax) { tmax = t.y; tidx = e0 + 1; }
    if (t.z > tmax) { tmax = t.z; tidx = e0 + 2; }
    if (t.w > tmax) { tmax = t.w; tidx = e0 + 3; }
}

__global__ __launch_bounds__(NTHREADS)
void dsnt_fused_kernel(const float* __restrict__ inp,
                       const float* __restrict__ tgt,
                       float* __restrict__ out) {
    const int blk = blockIdx.x;
    const float4* __restrict__ in4 = (const float4*)inp + (size_t)blk * QUART_F4;
    const float4* __restrict__ tg4 = (const float4*)tgt + (size_t)blk * QUART_F4;
    const int ebase = (blk & 3) << 14;   // element offset within map (quarter = 16384)

    float s = 0.f, sx = 0.f, sy = 0.f;
    float tmax = -1e30f;
    int   tidx = 0;

    // 4096 float4s / 256 threads = 16 strided slots, processed as 8 pairs.
    // Each iteration issues 4 independent global loads before any math (MLP>=4).
    #pragma unroll
    for (int it = 0; it < 8; ++it) {
        int j0 = threadIdx.x + it * (2 * NTHREADS);
        int j1 = j0 + NTHREADS;
        float4 a0 = in4[j0];
        float4 t0 = tg4[j0];
        float4 a1 = in4[j1];
        float4 t1 = tg4[j1];
        accum4(a0, t0, ebase + (j0 << 2), s, sx, sy, tmax, tidx);
        accum4(a1, t1, ebase + (j1 << 2), s, sx, sy, tmax, tidx);
    }

    // ---- warp reduction ----
    const unsigned FULL = 0xFFFFFFFFu;
    #pragma unroll
    for (int o = 16; o > 0; o >>= 1) {
        s  += __shfl_down_sync(FULL, s,  o);
        sx += __shfl_down_sync(FULL, sx, o);
        sy += __shfl_down_sync(FULL, sy, o);
        float om = __shfl_down_sync(FULL, tmax, o);
        int   oi = __shfl_down_sync(FULL, tidx, o);
        if (om > tmax || (om == tmax && oi < tidx)) { tmax = om; tidx = oi; }
    }

    // ---- cross-warp reduction (8 warps) ----
    __shared__ float sh_s [8];
    __shared__ float sh_sx[8];
    __shared__ float sh_sy[8];
    __shared__ float sh_m [8];
    __shared__ int   sh_i [8];
    __shared__ bool  isLast;

    const int lane = threadIdx.x & 31;
    const int wid  = threadIdx.x >> 5;
    if (lane == 0) {
        sh_s [wid] = s;  sh_sx[wid] = sx;  sh_sy[wid] = sy;
        sh_m [wid] = tmax;  sh_i [wid] = tidx;
    }
    __syncthreads();

    if (wid == 0) {
        s    = (lane < 8) ? sh_s [lane] : 0.f;
        sx   = (lane < 8) ? sh_sx[lane] : 0.f;
        sy   = (lane < 8) ? sh_sy[lane] : 0.f;
        tmax = (lane < 8) ? sh_m [lane] : -1e30f;
        tidx = (lane < 8) ? sh_i [lane] : 0x7FFFFFFF;
        #pragma unroll
        for (int o = 4; o > 0; o >>= 1) {
            s  += __shfl_down_sync(FULL, s,  o);
            sx += __shfl_down_sync(FULL, sx, o);
            sy += __shfl_down_sync(FULL, sy, o);
            float om = __shfl_down_sync(FULL, tmax, o);
            int   oi = __shfl_down_sync(FULL, tidx, o);
            if (om > tmax || (om == tmax && oi < tidx)) { tmax = om; tidx = oi; }
        }
        if (lane == 0) {
            g_s [blk] = s;  g_sx[blk] = sx;  g_sy[blk] = sy;
            g_m [blk] = tmax;  g_i [blk] = tidx;
            __threadfence();
            unsigned int prev = atomicAdd(&g_count, 1u);
            isLast = (prev == NBLOCKS - 1);
        }
    }
    __syncthreads();

    // ---- last block: combine 1024 partials -> 256 distances -> scalar ----
    if (isLast) {
        const int t = threadIdx.x;           // map index 0..255
        float S = 0.f, SX = 0.f, SY = 0.f;
        float M = -1e30f;
        int   I = 0;
        #pragma unroll
        for (int q = 0; q < 4; ++q) {        // ascending quarters: strict > keeps lowest index
            int b = 4 * t + q;
            S  += g_s [b];
            SX += g_sx[b];
            SY += g_sy[b];
            float m = g_m[b];
            if (m > M) { M = m; I = g_i[b]; }
        }

        float inv = 1.0f / (S * 256.0f);
        float px = SX * inv;
        float py = SY * inv;
        float tx = (float)((I & 255) + 1) * (1.0f / 256.0f);
        float ty = (float)((I >> 8)  + 1) * (1.0f / 256.0f);
        float dx = tx - px, dy = ty - py;
        float ed = sqrtf(dx * dx + dy * dy);

        // block-sum the 256 distances
        #pragma unroll
        for (int o = 16; o > 0; o >>= 1) ed += __shfl_down_sync(FULL, ed, o);
        __shared__ float sh_ed[8];
        if (lane == 0) sh_ed[wid] = ed;
        __syncthreads();
        if (wid == 0) {
            ed = (lane < 8) ? sh_ed[lane] : 0.f;
            #pragma unroll
            for (int o = 4; o > 0; o >>= 1) ed += __shfl_down_sync(FULL, ed, o);
            if (lane == 0) {
                out[0] = ed * (1.0f / 32.0f);
                g_count = 0;                 // reset for next graph replay
            }
        }
    }
}

extern "C" void kernel_launch(void* const* d_in, const int* in_sizes, int n_in,
                              void* d_out, int out_size) {
    const float* inp = (const float*)d_in[0];
    const float* tgt = (const float*)d_in[1];
    dsnt_fused_kernel<<<NBLOCKS, NTHREADS>>>(inp, tgt, (float*)d_out);
}

// round 4
// speedup vs baseline: 1.0609x; 1.0609x over previous
#include <cuda_runtime.h>

// Problem constants: B=32, C=8, H=256, W=256
#define NMAPS    256        // B*C, one block per map
#define NTHREADS 512
#define HW       65536
#define MAP_F4   16384      // float4s per map

// Per-block partials (no allocation: __device__ globals).
__device__ float        g_s [NMAPS];
__device__ float        g_sx[NMAPS];
__device__ float        g_sy[NMAPS];
__device__ float        g_m [NMAPS];
__device__ int          g_i [NMAPS];
__device__ unsigned int g_count = 0;

__global__ __launch_bounds__(NTHREADS)
void dsnt_fused_kernel(const float* __restrict__ inp,
                       const float* __restrict__ tgt,
                       float* __restrict__ out) {
    const int blk = blockIdx.x;
    const float4* __restrict__ in4 = (const float4*)inp + (size_t)blk * MAP_F4;
    const float4* __restrict__ tg4 = (const float4*)tgt + (size_t)blk * MAP_F4;

    float s = 0.f, sx = 0.f, sy = 0.f;
    float tmax = -1e30f;
    int   jbest = 0;
    float wx = 0.f, wy = 0.f, wz = 0.f, ww = 0.f;   // winning float4

    // 16384 float4s / 512 threads = 32 iterations, coalesced stride.
    #pragma unroll 4
    for (int j = threadIdx.x; j < MAP_F4; j += NTHREADS) {
        float4 a = in4[j];
        float4 t = tg4[j];
        int e0  = j << 2;
        int col = e0 & 255;
        int row = e0 >> 8;

        float ex = __expf(a.x);
        float ey = __expf(a.y);
        float ez = __expf(a.z);
        float ew = __expf(a.w);
        float es = (ex + ey) + (ez + ew);

        s  += es;
        sy  = fmaf(es, (float)(row + 1), sy);
        // ex*(c+1)+ey*(c+2)+ez*(c+3)+ew*(c+4) = es*(c+1) + ey + 2ez + 3ew
        float extra = fmaf(2.f, ez, ey);
        extra = fmaf(3.f, ew, extra);
        sx += fmaf(es, (float)(col + 1), extra);

        // argmax: tree max (short FMNMX chain) + single conditional update.
        // strict > with ascending j keeps the earliest j on ties.
        float v = fmaxf(fmaxf(t.x, t.y), fmaxf(t.z, t.w));
        if (v > tmax) {
            tmax = v; jbest = j;
            wx = t.x; wy = t.y; wz = t.z; ww = t.w;
        }
    }

    // reconstruct element index within the winning float4 (first match wins)
    int c = (wx == tmax) ? 0 : (wy == tmax) ? 1 : (wz == tmax) ? 2 : 3;
    int tidx = (jbest << 2) + c;

    // ---- warp reduction ----
    const unsigned FULL = 0xFFFFFFFFu;
    #pragma unroll
    for (int o = 16; o > 0; o >>= 1) {
        s  += __shfl_down_sync(FULL, s,  o);
        sx += __shfl_down_sync(FULL, sx, o);
        sy += __shfl_down_sync(FULL, sy, o);
        float om = __shfl_down_sync(FULL, tmax, o);
        int   oi = __shfl_down_sync(FULL, tidx, o);
        if (om > tmax || (om == tmax && oi < tidx)) { tmax = om; tidx = oi; }
    }

    // ---- cross-warp reduction (16 warps) ----
    __shared__ float sh_s [16];
    __shared__ float sh_sx[16];
    __shared__ float sh_sy[16];
    __shared__ float sh_m [16];
    __shared__ int   sh_i [16];
    __shared__ bool  isLast;

    const int lane = threadIdx.x & 31;
    const int wid  = threadIdx.x >> 5;
    if (lane == 0) {
        sh_s [wid] = s;  sh_sx[wid] = sx;  sh_sy[wid] = sy;
        sh_m [wid] = tmax;  sh_i [wid] = tidx;
    }
    __syncthreads();

    if (wid == 0) {
        s    = (lane < 16) ? sh_s [lane] : 0.f;
        sx   = (lane < 16) ? sh_sx[lane] : 0.f;
        sy   = (lane < 16) ? sh_sy[lane] : 0.f;
        tmax = (lane < 16) ? sh_m [lane] : -1e30f;
        tidx = (lane < 16) ? sh_i [lane] : 0x7FFFFFFF;
        #pragma unroll
        for (int o = 8; o > 0; o >>= 1) {
            s  += __shfl_down_sync(FULL, s,  o);
            sx += __shfl_down_sync(FULL, sx, o);
            sy += __shfl_down_sync(FULL, sy, o);
            float om = __shfl_down_sync(FULL, tmax, o);
            int   oi = __shfl_down_sync(FULL, tidx, o);
            if (om > tmax || (om == tmax && oi < tidx)) { tmax = om; tidx = oi; }
        }
        if (lane == 0) {
            g_s [blk] = s;  g_sx[blk] = sx;  g_sy[blk] = sy;
            g_m [blk] = tmax;  g_i [blk] = tidx;
            __threadfence();
            unsigned int prev = atomicAdd(&g_count, 1u);
            isLast = (prev == NMAPS - 1);
        }
    }
    __syncthreads();

    // ---- last block: 256 per-map partials -> distances -> scalar ----
    if (isLast) {
        __threadfence();                      // acquire all blocks' partials
        const int t = threadIdx.x;
        float ed = 0.f;
        if (t < NMAPS) {
            float S  = g_s [t];
            float SX = g_sx[t];
            float SY = g_sy[t];
            int   I  = g_i [t];

            float inv = 1.0f / (S * 256.0f);
            float px = SX * inv;
            float py = SY * inv;
            float tx = (float)((I & 255) + 1) * (1.0f / 256.0f);
            float ty = (float)((I >> 8)  + 1) * (1.0f / 256.0f);
            float dx = tx - px, dy = ty - py;
            ed = sqrtf(dx * dx + dy * dy);
        }

        // block-sum the 256 distances across all 16 warps
        #pragma unroll
        for (int o = 16; o > 0; o >>= 1) ed += __shfl_down_sync(FULL, ed, o);
        __shared__ float sh_ed[16];
        if (lane == 0) sh_ed[wid] = ed;
        __syncthreads();
        if (wid == 0) {
            ed = (lane < 16) ? sh_ed[lane] : 0.f;
            #pragma unroll
            for (int o = 8; o > 0; o >>= 1) ed += __shfl_down_sync(FULL, ed, o);
            if (lane == 0) {
                out[0] = ed * (1.0f / 32.0f);
                g_count = 0;                  // reset for next graph replay
            }
        }
    }
}

extern "C" void kernel_launch(void* const* d_in, const int* in_sizes, int n_in,
                              void* d_out, int out_size) {
    const float* inp = (const float*)d_in[0];
    const float* tgt = (const float*)d_in[1];
    dsnt_fused_kernel<<<NMAPS, NTHREADS>>>(inp, tgt, (float*)d_out);
}

// round 5
// speedup vs baseline: 1.1498x; 1.0837x over previous
#include <cuda_runtime.h>
#include <cstdint>

// Problem constants: B=32, C=8, H=256, W=256
#define NMAPS    256
#define NBLK     512          // 2 half-map blocks per map
#define NTHR     256
#define HALF_F4  8192         // float4s per half-map (32768 floats)
#define CHUNK_F4 512          // float4s per chunk (2048 floats)
#define NCHUNK   16           // chunks per half-map
#define NSTAGES  3
#define TGT_OFF  (NSTAGES * CHUNK_F4)          // tgt stages after inp stages (in float4s)
#define RED_OFF  (2 * NSTAGES * CHUNK_F4)      // reduction scratch after both (3072 f4 = 48KB)
#define SMEM_BYTES (RED_OFF * 16 + 256)

// Per-block partials (no allocation: __device__ globals).
__device__ float        g_s [NBLK];
__device__ float        g_sx[NBLK];
__device__ float        g_sy[NBLK];
__device__ float        g_m [NBLK];
__device__ int          g_i [NBLK];
__device__ unsigned int g_count = 0;

__device__ __forceinline__ void cp16(float4* dst_smem, const float4* src) {
    uint32_t d = (uint32_t)__cvta_generic_to_shared(dst_smem);
    asm volatile("cp.async.cg.shared.global [%0], [%1], 16;\n" :: "r"(d), "l"(src));
}

__device__ __forceinline__ void accum4(float4 a, float4 t, int e0,
                                       float& s, float& sx, float& sy,
                                       float& tmax, int& ebest,
                                       float& wx, float& wy, float& wz, float& ww) {
    int col = e0 & 255;
    int row = e0 >> 8;
    float ex = __expf(a.x);
    float ey = __expf(a.y);
    float ez = __expf(a.z);
    float ew = __expf(a.w);
    float es = (ex + ey) + (ez + ew);
    s  += es;
    sy  = fmaf(es, (float)(row + 1), sy);
    float extra = fmaf(2.f, ez, ey);
    extra = fmaf(3.f, ew, extra);
    sx += fmaf(es, (float)(col + 1), extra);
    // tree max + single conditional keep; strict > with ascending e0 keeps first index
    float v = fmaxf(fmaxf(t.x, t.y), fmaxf(t.z, t.w));
    if (v > tmax) { tmax = v; ebest = e0; wx = t.x; wy = t.y; wz = t.z; ww = t.w; }
}

__global__ __launch_bounds__(NTHR)
void dsnt_pipe_kernel(const float* __restrict__ inp,
                      const float* __restrict__ tgt,
                      float* __restrict__ out) {
    extern __shared__ float4 sm[];
    const int blk = blockIdx.x;
    const int tid = threadIdx.x;
    const float4* __restrict__ in4 = (const float4*)inp + (size_t)blk * HALF_F4;
    const float4* __restrict__ tg4 = (const float4*)tgt + (size_t)blk * HALF_F4;
    const int ebase = (blk & 1) << 15;     // element offset within the map

    // ---- private 3-stage pipeline: thread tid owns f4 slots {tid, tid+256} of each chunk ----
    // prologue: stages 0,1
    #pragma unroll
    for (int k = 0; k < NSTAGES - 1; ++k) {
        int b = k * CHUNK_F4;
        cp16(&sm[k * CHUNK_F4 + tid],                 in4 + b + tid);
        cp16(&sm[k * CHUNK_F4 + tid + NTHR],          in4 + b + tid + NTHR);
        cp16(&sm[TGT_OFF + k * CHUNK_F4 + tid],        tg4 + b + tid);
        cp16(&sm[TGT_OFF + k * CHUNK_F4 + tid + NTHR], tg4 + b + tid + NTHR);
        asm volatile("cp.async.commit_group;\n" ::: "memory");
    }

    float s = 0.f, sx = 0.f, sy = 0.f;
    float tmax = -1e30f;
    int   ebest = 0;
    float wx = 0.f, wy = 0.f, wz = 0.f, ww = 0.f;

    #pragma unroll
    for (int k = 0; k < NCHUNK; ++k) {
        const int slot = k % NSTAGES;
        // wait until my oldest pending group (chunk k) is complete
        asm volatile("cp.async.wait_group %0;\n" :: "n"(NSTAGES - 2) : "memory");

        float4 a0 = sm[slot * CHUNK_F4 + tid];
        float4 a1 = sm[slot * CHUNK_F4 + tid + NTHR];
        float4 t0 = sm[TGT_OFF + slot * CHUNK_F4 + tid];
        float4 t1 = sm[TGT_OFF + slot * CHUNK_F4 + tid + NTHR];

        int e0 = ebase + ((k * CHUNK_F4 + tid) << 2);
        int e1 = ebase + ((k * CHUNK_F4 + tid + NTHR) << 2);
        accum4(a0, t0, e0, s, sx, sy, tmax, ebest, wx, wy, wz, ww);
        accum4(a1, t1, e1, s, sx, sy, tmax, ebest, wx, wy, wz, ww);

        // refill this thread's slots for chunk k+NSTAGES-1 (thread-private, no barrier needed)
        const int kn = k + NSTAGES - 1;
        if (kn < NCHUNK) {
            const int sl = kn % NSTAGES;
            int b = kn * CHUNK_F4;
            cp16(&sm[sl * CHUNK_F4 + tid],                 in4 + b + tid);
            cp16(&sm[sl * CHUNK_F4 + tid + NTHR],          in4 + b + tid + NTHR);
            cp16(&sm[TGT_OFF + sl * CHUNK_F4 + tid],        tg4 + b + tid);
            cp16(&sm[TGT_OFF + sl * CHUNK_F4 + tid + NTHR], tg4 + b + tid + NTHR);
        }
        asm volatile("cp.async.commit_group;\n" ::: "memory");
    }

    // reconstruct element index within the winning float4 (first match wins)
    int c = (wx == tmax) ? 0 : (wy == tmax) ? 1 : (wz == tmax) ? 2 : 3;
    int tidx = ebest + c;

    // ---- warp reduction ----
    const unsigned FULL = 0xFFFFFFFFu;
    #pragma unroll
    for (int o = 16; o > 0; o >>= 1) {
        s  += __shfl_down_sync(FULL, s,  o);
        sx += __shfl_down_sync(FULL, sx, o);
        sy += __shfl_down_sync(FULL, sy, o);
        float om = __shfl_down_sync(FULL, tmax, o);
        int   oi = __shfl_down_sync(FULL, tidx, o);
        if (om > tmax || (om == tmax && oi < tidx)) { tmax = om; tidx = oi; }
    }

    // ---- cross-warp reduction (8 warps) via scratch past the stage buffers ----
    float* red = (float*)(sm + RED_OFF);
    float* sh_s  = red;          // [8]
    float* sh_sx = red + 8;      // [8]
    float* sh_sy = red + 16;     // [8]
    float* sh_m  = red + 24;     // [8]
    int*   sh_i  = (int*)(red + 32);   // [8]
    int*   sh_fl = (int*)(red + 40);   // isLast flag
    float* sh_ed = red + 48;     // [8]

    const int lane = tid & 31;
    const int wid  = tid >> 5;
    if (lane == 0) {
        sh_s [wid] = s;  sh_sx[wid] = sx;  sh_sy[wid] = sy;
        sh_m [wid] = tmax;  sh_i [wid] = tidx;
    }
    __syncthreads();

    if (wid == 0) {
        s    = (lane < 8) ? sh_s [lane] : 0.f;
        sx   = (lane < 8) ? sh_sx[lane] : 0.f;
        sy   = (lane < 8) ? sh_sy[lane] : 0.f;
        tmax = (lane < 8) ? sh_m [lane] : -1e30f;
        tidx = (lane < 8) ? sh_i [lane] : 0x7FFFFFFF;
        #pragma unroll
        for (int o = 4; o > 0; o >>= 1) {
            s  += __shfl_down_sync(FULL, s,  o);
            sx += __shfl_down_sync(FULL, sx, o);
            sy += __shfl_down_sync(FULL, sy, o);
            float om = __shfl_down_sync(FULL, tmax, o);
            int   oi = __shfl_down_sync(FULL, tidx, o);
            if (om > tmax || (om == tmax && oi < tidx)) { tmax = om; tidx = oi; }
        }
        if (lane == 0) {
            g_s [blk] = s;  g_sx[blk] = sx;  g_sy[blk] = sy;
            g_m [blk] = tmax;  g_i [blk] = tidx;
            __threadfence();
            unsigned int prev = atomicAdd(&g_count, 1u);
            sh_fl[0] = (prev == NBLK - 1) ? 1 : 0;
        }
    }
    __syncthreads();

    // ---- last block: combine 512 partials -> 256 distances -> scalar ----
    if (sh_fl[0]) {
        __threadfence();                  // acquire all blocks' partials
        const int t = tid;                // map index 0..255
        float s0  = g_s [2*t],   s1  = g_s [2*t+1];
        float sx0 = g_sx[2*t],   sx1 = g_sx[2*t+1];
        float sy0 = g_sy[2*t],   sy1 = g_sy[2*t+1];
        float m0  = g_m [2*t],   m1  = g_m [2*t+1];
        int   i0  = g_i [2*t],   i1  = g_i [2*t+1];

        float S  = s0 + s1;
        float SX = sx0 + sx1;
        float SY = sy0 + sy1;
        int   I  = (m1 > m0) ? i1 : i0;   // first half has lower indices

        float inv = 1.0f / (S * 256.0f);
        float px = SX * inv;
        float py = SY * inv;
        float tx = (float)((I & 255) + 1) * (1.0f / 256.0f);
        float ty = (float)((I >> 8)  + 1) * (1.0f / 256.0f);
        float dx = tx - px, dy = ty - py;
        float ed = sqrtf(dx * dx + dy * dy);

        #pragma unroll
        for (int o = 16; o > 0; o >>= 1) ed += __shfl_down_sync(FULL, ed, o);
        if (lane == 0) sh_ed[wid] = ed;
        __syncthreads();
        if (wid == 0) {
            ed = (lane < 8) ? sh_ed[lane] : 0.f;
            #pragma unroll
            for (int o = 4; o > 0; o >>= 1) ed += __shfl_down_sync(FULL, ed, o);
            if (lane == 0) {
                out[0] = ed * (1.0f / 32.0f);
                g_count = 0;              // reset for next graph replay
            }
        }
    }
}

extern "C" void kernel_launch(void* const* d_in, const int* in_sizes, int n_in,
                              void* d_out, int out_size) {
    const float* inp = (const float*)d_in[0];
    const float* tgt = (const float*)d_in[1];
    static bool attr_set = false;
    if (!attr_set) {
        cudaFuncSetAttribute(dsnt_pipe_kernel,
                             cudaFuncAttributeMaxDynamicSharedMemorySize, SMEM_BYTES);
        attr_set = true;
    }
    dsnt_pipe_kernel<<<NBLK, NTHR, SMEM_BYTES>>>(inp, tgt, (float*)d_out);
}